// round 14
// baseline (speedup 1.0000x reference)
#include <cuda_runtime.h>
#include <math.h>
#include <stdint.h>

#define NB   4
#define HH   128
#define WW   128
#define CC   128
#define GG   8
#define GC   16
#define KK   9
#define NTOK (NB * HH * WW)   // 65536
#define HID  512
#define NOM  256              // padded offset(144)+mask(72) combined width
#define EPS  1e-5f

// ---------------- scratch (device globals; no allocation allowed) ------------
__device__ float g_xn [NTOK * CC];
__device__ float g_xp [NTOK * CC];
__device__ float g_x1 [NTOK * CC];
__device__ float g_om [NTOK * NOM];
__device__ float g_y  [NTOK * CC];
__device__ float g_x2 [NTOK * CC];
__device__ float g_h  [NTOK * CC];
__device__ float g_h1 [NTOK * HID];
__device__ float g_wcat[CC * NOM];       // [K=128][256] packed off_w|mask_w|0
__device__ float g_bcat[NOM];

__device__ __forceinline__ float gelu_exact(float x) {
    return 0.5f * x * (1.0f + erff(x * 0.70710678118654752f));
}

__device__ __forceinline__ void mma_tf32(float c[4], const uint32_t a[4], const uint32_t b[2]) {
    asm volatile(
        "mma.sync.aligned.m16n8k8.row.col.f32.tf32.tf32.f32 "
        "{%0,%1,%2,%3}, {%4,%5,%6,%7}, {%8,%9}, {%0,%1,%2,%3};"
        : "+f"(c[0]), "+f"(c[1]), "+f"(c[2]), "+f"(c[3])
        : "r"(a[0]), "r"(a[1]), "r"(a[2]), "r"(a[3]), "r"(b[0]), "r"(b[1]));
}

__device__ __forceinline__ void ldsm_x4(uint32_t& r0, uint32_t& r1, uint32_t& r2, uint32_t& r3,
                                        uint32_t addr) {
    asm volatile("ldmatrix.sync.aligned.m8n8.x4.shared.b16 {%0,%1,%2,%3}, [%4];"
                 : "=r"(r0), "=r"(r1), "=r"(r2), "=r"(r3) : "r"(addr));
}

__device__ __forceinline__ void cp_async16(uint32_t dst_smem, const void* src) {
    asm volatile("cp.async.cg.shared.global [%0], [%1], 16;" :: "r"(dst_smem), "l"(src));
}
__device__ __forceinline__ void cp_commit() { asm volatile("cp.async.commit_group;"); }
template <int N> __device__ __forceinline__ void cp_wait() {
    asm volatile("cp.async.wait_group %0;" :: "n"(N));
}

// ---------------- weight-packing prep: wcat = [off_w | mask_w | 0] ----------
__global__ __launch_bounds__(256) void prep_offmask_kernel(
    const float* __restrict__ off_w, const float* __restrict__ off_b,
    const float* __restrict__ mask_w, const float* __restrict__ mask_b,
    float* __restrict__ wcat, float* __restrict__ bcat)
{
    const int k = blockIdx.x;
    const int j = threadIdx.x;
    float v = 0.0f;
    if (j < 144)      v = off_w[k * 144 + j];
    else if (j < 216) v = mask_w[k * 72 + (j - 144)];
    wcat[k * NOM + j] = v;
    if (k == 0) {
        float bv = 0.0f;
        if (j < 144)      bv = off_b[j];
        else if (j < 216) bv = mask_b[j - 144];
        bcat[j] = bv;
    }
}

// -------- LayerNorm, warp per token, float4, shfl-only reduction ------------
__global__ __launch_bounds__(256) void ln_v4_kernel(
    const float* __restrict__ in, const float* __restrict__ g,
    const float* __restrict__ b, float* __restrict__ out)
{
    const int warp = threadIdx.x >> 5;
    const int lane = threadIdx.x & 31;
    const int tok  = blockIdx.x * 8 + warp;

    const float4 v = *(const float4*)&in[(size_t)tok * CC + lane * 4];
    float s  = v.x + v.y + v.z + v.w;
    float s2 = v.x * v.x + v.y * v.y + v.z * v.z + v.w * v.w;
    #pragma unroll
    for (int o = 16; o > 0; o >>= 1) {
        s  += __shfl_xor_sync(0xffffffffu, s,  o);
        s2 += __shfl_xor_sync(0xffffffffu, s2, o);
    }
    const float mean = s * (1.0f / CC);
    const float var  = s2 * (1.0f / CC) - mean * mean;
    const float rstd = rsqrtf(var + EPS);
    const float4 gg = *(const float4*)&g[lane * 4];
    const float4 bb = *(const float4*)&b[lane * 4];
    float4 o4;
    o4.x = (v.x - mean) * rstd * gg.x + bb.x;
    o4.y = (v.y - mean) * rstd * gg.y + bb.y;
    o4.z = (v.z - mean) * rstd * gg.z + bb.z;
    o4.w = (v.w - mean) * rstd * gg.w + bb.w;
    *(float4*)&out[(size_t)tok * CC + lane * 4] = o4;
}

// ------ dwconv3x3 + LN + GELU v5: warp per 8-token row segment, rolling -----
// Each warp: tokens (n, h, w0..w0+7); lane = channel quad. Rolling 3-column
// register window; 30 column-loads per 8 tokens (vs 72 naive). FMA order
// preserved (ky outer, kx inner) -> bit-identical to v4.
__global__ __launch_bounds__(256) void dwconv_ln_gelu_v5_kernel(
    const float* __restrict__ xn, const float* __restrict__ dwk,
    const float* __restrict__ dwb, const float* __restrict__ lg,
    const float* __restrict__ lb, float* __restrict__ out)
{
    const int warp = threadIdx.x >> 5;
    const int lane = threadIdx.x & 31;
    const int seg  = blockIdx.x * 8 + warp;          // 8192 segments
    const int row  = seg >> 4;                       // n*HH + h  (0..511)
    const int w0   = (seg & 15) * 8;
    const int h    = row & (HH - 1);
    const int c4   = lane * 4;

    const float* rowc = xn + ((size_t)row * WW) * CC + c4;       // row h
    const bool hup = (h >= 1), hdn = (h <= HH - 2);

    // kernel weights: 9 float4, loaded once
    float4 wk[9];
    #pragma unroll
    for (int t = 0; t < 9; t++) wk[t] = *(const float4*)&dwk[t * CC + c4];
    const float4 bia = *(const float4*)&dwb[c4];
    const float4 gg  = *(const float4*)&lg[c4];
    const float4 bb  = *(const float4*)&lb[c4];

    const float4 z4 = make_float4(0.f, 0.f, 0.f, 0.f);
    float4 cL[3], cC[3], cR[3];

    // load a column (3 rows) at width index wx; zero outside image
    auto load_col = [&](int wx, float4 v[3]) {
        if (wx < 0 || wx >= WW) { v[0] = z4; v[1] = z4; v[2] = z4; return; }
        const int off = wx * CC;
        v[0] = hup ? *(const float4*)(rowc + off - WW * CC) : z4;
        v[1] = *(const float4*)(rowc + off);
        v[2] = hdn ? *(const float4*)(rowc + off + WW * CC) : z4;
    };

    load_col(w0 - 1, cL);
    load_col(w0,     cC);

    #pragma unroll
    for (int t = 0; t < 8; t++) {
        load_col(w0 + t + 1, cR);

        float4 acc = bia;
        #pragma unroll
        for (int ky = 0; ky < 3; ky++) {
            const float4 k0 = wk[ky * 3 + 0], k1 = wk[ky * 3 + 1], k2 = wk[ky * 3 + 2];
            acc.x = fmaf(cL[ky].x, k0.x, acc.x);
            acc.y = fmaf(cL[ky].y, k0.y, acc.y);
            acc.z = fmaf(cL[ky].z, k0.z, acc.z);
            acc.w = fmaf(cL[ky].w, k0.w, acc.w);
            acc.x = fmaf(cC[ky].x, k1.x, acc.x);
            acc.y = fmaf(cC[ky].y, k1.y, acc.y);
            acc.z = fmaf(cC[ky].z, k1.z, acc.z);
            acc.w = fmaf(cC[ky].w, k1.w, acc.w);
            acc.x = fmaf(cR[ky].x, k2.x, acc.x);
            acc.y = fmaf(cR[ky].y, k2.y, acc.y);
            acc.z = fmaf(cR[ky].z, k2.z, acc.z);
            acc.w = fmaf(cR[ky].w, k2.w, acc.w);
        }

        // LN over 128 channels (warp shfl, same order as v4)
        float s  = acc.x + acc.y + acc.z + acc.w;
        float s2 = acc.x * acc.x + acc.y * acc.y + acc.z * acc.z + acc.w * acc.w;
        #pragma unroll
        for (int o = 16; o > 0; o >>= 1) {
            s  += __shfl_xor_sync(0xffffffffu, s,  o);
            s2 += __shfl_xor_sync(0xffffffffu, s2, o);
        }
        const float mean = s * (1.0f / CC);
        const float var  = s2 * (1.0f / CC) - mean * mean;
        const float rstd = rsqrtf(var + EPS);
        float4 o4;
        o4.x = gelu_exact((acc.x - mean) * rstd * gg.x + bb.x);
        o4.y = gelu_exact((acc.y - mean) * rstd * gg.y + bb.y);
        o4.z = gelu_exact((acc.z - mean) * rstd * gg.z + bb.z);
        o4.w = gelu_exact((acc.w - mean) * rstd * gg.w + bb.w);
        *(float4*)&out[((size_t)row * WW + w0 + t) * CC + c4] = o4;

        #pragma unroll
        for (int ky = 0; ky < 3; ky++) { cL[ky] = cC[ky]; cC[ky] = cR[ky]; }
    }
}

// ---- tf32 GEMM (R11 config: ldmatrix A, LDS B) + optional fused-LN epilogue
// BM=128, BN=128, BK=32; 256 thr = 8 warps (2 M x 4 N), warp tile 64x32.
// act: 0 = none, 1 = gelu, 2 = (res add, write C=x2) + LN -> D.
#define AS_STRIDE 36
#define BS_STRIDE 136
#define A_BUF (128 * AS_STRIDE)
#define B_BUF (32 * BS_STRIDE)
#define GEMM_SMEM_BYTES ((2 * A_BUF + 2 * B_BUF) * 4)   // 71680
#define SX_STRIDE 132

__global__ __launch_bounds__(256) void gemm_tf32_db_kernel(
    const float* __restrict__ A, const float* __restrict__ B,
    const float* __restrict__ bias, const float* __restrict__ res,
    float* __restrict__ C, float* __restrict__ D,
    const float* __restrict__ g2, const float* __restrict__ b2,
    int M, int N, int K, int act)
{
    extern __shared__ float smem[];
    float* sA = smem;
    float* sB = smem + 2 * A_BUF;

    const int tid  = threadIdx.x;
    const int warp = tid >> 5;
    const int lane = tid & 31;
    const int grp  = lane >> 2;
    const int t4   = lane & 3;
    const int wm   = warp >> 2;
    const int wn   = warp & 3;
    const int brow = blockIdx.y * 128;
    const int bcol = blockIdx.x * 128;

    const uint32_t sA_u = (uint32_t)__cvta_generic_to_shared(sA);
    const uint32_t sB_u = (uint32_t)__cvta_generic_to_shared(sB);
    const int KT = K >> 5;

    const int a_row = ((lane >> 3) & 1) * 8 + (lane & 7);
    const int a_col = (lane >> 4) * 4;

    auto load_tile = [&](int kt, int buf) {
        const int k0 = kt << 5;
        #pragma unroll
        for (int it = 0; it < 4; it++) {
            const int idx = it * 256 + tid;
            const int r = idx >> 3, c = idx & 7;
            cp_async16(sA_u + (buf * A_BUF + r * AS_STRIDE + c * 4) * 4,
                       &A[(size_t)(brow + r) * K + k0 + c * 4]);
        }
        #pragma unroll
        for (int it = 0; it < 4; it++) {
            const int idx = it * 256 + tid;
            const int kr = idx >> 5, c = idx & 31;
            cp_async16(sB_u + (buf * B_BUF + kr * BS_STRIDE + c * 4) * 4,
                       &B[(size_t)(k0 + kr) * N + bcol + c * 4]);
        }
        cp_commit();
    };

    float acc[4][4][4];
    #pragma unroll
    for (int i = 0; i < 4; i++)
        #pragma unroll
        for (int j = 0; j < 4; j++)
            #pragma unroll
            for (int q = 0; q < 4; q++) acc[i][j][q] = 0.0f;

    load_tile(0, 0);

    for (int kt = 0; kt < KT; kt++) {
        if (kt + 1 < KT) { load_tile(kt + 1, (kt + 1) & 1); cp_wait<1>(); }
        else             { cp_wait<0>(); }
        __syncthreads();

        const uint32_t Ab_u = sA_u + ((kt & 1) * A_BUF) * 4;
        const float*   Bb   = sB + (kt & 1) * B_BUF;

        #pragma unroll
        for (int kk = 0; kk < 4; kk++) {
            const int kb = kk * 8;
            uint32_t af[4][4], bf[4][2];
            #pragma unroll
            for (int i = 0; i < 4; i++) {
                const int m0 = wm * 64 + i * 16;
                ldsm_x4(af[i][0], af[i][1], af[i][2], af[i][3],
                        Ab_u + ((m0 + a_row) * AS_STRIDE + kb + a_col) * 4);
            }
            #pragma unroll
            for (int j = 0; j < 4; j++) {
                const int n0 = wn * 32 + j * 8 + grp;
                bf[j][0] = __float_as_uint(Bb[(kb + t4    ) * BS_STRIDE + n0]);
                bf[j][1] = __float_as_uint(Bb[(kb + t4 + 4) * BS_STRIDE + n0]);
            }
            #pragma unroll
            for (int i = 0; i < 4; i++)
                #pragma unroll
                for (int j = 0; j < 4; j++)
                    mma_tf32(acc[i][j], af[i], bf[j]);
        }
        __syncthreads();
    }

    if (act == 2) {
        float* sx = smem;   // dead tile buffers; [128][SX_STRIDE]
        #pragma unroll
        for (int i = 0; i < 4; i++) {
            const int rl0 = wm * 64 + i * 16 + grp;
            #pragma unroll
            for (int j = 0; j < 4; j++) {
                const int col = wn * 32 + j * 8 + 2 * t4;
                const float b0 = bias[col], b1 = bias[col + 1];
                #pragma unroll
                for (int half = 0; half < 2; half++) {
                    const int rl = rl0 + half * 8;
                    const int r  = brow + rl;
                    const float2 rr = *(const float2*)&res[(size_t)r * N + col];
                    const float v0 = acc[i][j][half * 2 + 0] + b0 + rr.x;
                    const float v1 = acc[i][j][half * 2 + 1] + b1 + rr.y;
                    *(float2*)&C[(size_t)r * N + col] = make_float2(v0, v1);
                    *(float2*)&sx[rl * SX_STRIDE + col] = make_float2(v0, v1);
                }
            }
        }
        __syncthreads();
        const float4 g4 = *(const float4*)&g2[lane * 4];
        const float4 b4 = *(const float4*)&b2[lane * 4];
        #pragma unroll
        for (int rr2 = 0; rr2 < 16; rr2++) {
            const int rl = warp * 16 + rr2;
            const float4 v = *(const float4*)&sx[rl * SX_STRIDE + lane * 4];
            float s  = v.x + v.y + v.z + v.w;
            float q  = v.x * v.x + v.y * v.y + v.z * v.z + v.w * v.w;
            #pragma unroll
            for (int o = 16; o > 0; o >>= 1) {
                s += __shfl_xor_sync(0xffffffffu, s, o);
                q += __shfl_xor_sync(0xffffffffu, q, o);
            }
            const float mean = s * (1.0f / CC);
            const float var  = q * (1.0f / CC) - mean * mean;
            const float rstd = rsqrtf(var + EPS);
            float4 o4;
            o4.x = (v.x - mean) * rstd * g4.x + b4.x;
            o4.y = (v.y - mean) * rstd * g4.y + b4.y;
            o4.z = (v.z - mean) * rstd * g4.z + b4.z;
            o4.w = (v.w - mean) * rstd * g4.w + b4.w;
            *(float4*)&D[(size_t)(brow + rl) * CC + lane * 4] = o4;
        }
        return;
    }

    #pragma unroll
    for (int i = 0; i < 4; i++) {
        const int r0 = brow + wm * 64 + i * 16 + grp;
        #pragma unroll
        for (int j = 0; j < 4; j++) {
            const int col = bcol + wn * 32 + j * 8 + 2 * t4;
            const float b0 = bias[col], b1 = bias[col + 1];
            #pragma unroll
            for (int half = 0; half < 2; half++) {
                const int r = r0 + half * 8;
                float v0 = acc[i][j][half * 2 + 0] + b0;
                float v1 = acc[i][j][half * 2 + 1] + b1;
                if (act == 1) { v0 = gelu_exact(v0); v1 = gelu_exact(v1); }
                if (res) {
                    const float2 rr = *(const float2*)&res[(size_t)r * N + col];
                    v0 += rr.x; v1 += rr.y;
                }
                *(float2*)&C[(size_t)r * N + col] = make_float2(v0, v1);
            }
        }
    }
}

// ------- deformable sampling + fused softmax; 1 warp per token, float4 ------
__global__ __launch_bounds__(128) void dcn_sample_kernel(
    const float* __restrict__ xp, const float* __restrict__ om,
    float* __restrict__ y)
{
    const int tt   = threadIdx.x >> 5;
    const int lane = threadIdx.x & 31;
    const int tok  = blockIdx.x * 4 + tt;
    const int n  = tok / (HH * WW);
    const int hw = tok % (HH * WW);
    const int h = hw / WW, w = hw % WW;

    __shared__ float s_om[4][216];
    const float* src = om + (size_t)tok * NOM;
    for (int i = lane; i < 216; i += 32) s_om[tt][i] = src[i];
    __syncwarp();

    if (lane < GG) {
        float* p = &s_om[tt][144 + lane * KK];
        float mx = -1e30f;
        #pragma unroll
        for (int k = 0; k < KK; k++) mx = fmaxf(mx, p[k]);
        float s = 0.0f, e[KK];
        #pragma unroll
        for (int k = 0; k < KK; k++) { e[k] = __expf(p[k] - mx); s += e[k]; }
        const float inv = 1.0f / s;
        #pragma unroll
        for (int k = 0; k < KK; k++) p[k] = e[k] * inv;
    }
    __syncwarp();

    const int g  = lane >> 2;
    const int c4 = lane & 3;
    const float* base = xp + ((size_t)n * HH * WW) * CC + g * GC + c4 * 4;
    float4 acc = make_float4(0.f, 0.f, 0.f, 0.f);

    #pragma unroll
    for (int k = 0; k < KK; k++) {
        const float ox = s_om[tt][(g * KK + k) * 2 + 0];
        const float oy = s_om[tt][(g * KK + k) * 2 + 1];
        const float mw = s_om[tt][144 + g * KK + k];
        const float px = (float)(w + 1 + (k / 3) - 1) + ox;
        const float py = (float)(h + 1 + (k % 3) - 1) + oy;
        const float x0f = floorf(px), y0f = floorf(py);
        const float tx = px - x0f, ty = py - y0f;
        const int x0 = (int)x0f, y0 = (int)y0f;

        const bool yi0 = (y0 >= 1) & (y0 <= HH);
        const bool yi1 = (y0 + 1 >= 1) & (y0 + 1 <= HH);
        const bool xi0 = (x0 >= 1) & (x0 <= WW);
        const bool xi1 = (x0 + 1 >= 1) & (x0 + 1 <= WW);

        float4 v00 = make_float4(0,0,0,0), v01 = v00, v10 = v00, v11 = v00;
        if (yi0 & xi0) v00 = *(const float4*)&base[((size_t)(y0 - 1) * WW + (x0 - 1)) * CC];
        if (yi0 & xi1) v01 = *(const float4*)&base[((size_t)(y0 - 1) * WW + (x0    )) * CC];
        if (yi1 & xi0) v10 = *(const float4*)&base[((size_t)(y0    ) * WW + (x0 - 1)) * CC];
        if (yi1 & xi1) v11 = *(const float4*)&base[((size_t)(y0    ) * WW + (x0    )) * CC];

        const float w00 = mw * (1.f - ty) * (1.f - tx);
        const float w01 = mw * (1.f - ty) * tx;
        const float w10 = mw * ty * (1.f - tx);
        const float w11 = mw * ty * tx;
        acc.x += w00 * v00.x + w01 * v01.x + w10 * v10.x + w11 * v11.x;
        acc.y += w00 * v00.y + w01 * v01.y + w10 * v10.y + w11 * v11.y;
        acc.z += w00 * v00.z + w01 * v01.z + w10 * v10.z + w11 * v11.z;
        acc.w += w00 * v00.w + w01 * v01.w + w10 * v10.w + w11 * v11.w;
    }
    *(float4*)&y[(size_t)tok * CC + g * GC + c4 * 4] = acc;
}

// ---------------------------------------------------------------------------
extern "C" void kernel_launch(void* const* d_in, const int* in_sizes, int n_in,
                              void* d_out, int out_size)
{
    const float* x      = (const float*)d_in[0];
    const float* ln1_g  = (const float*)d_in[1];
    const float* ln1_b  = (const float*)d_in[2];
    const float* in_w   = (const float*)d_in[3];
    const float* in_b   = (const float*)d_in[4];
    const float* dw_k   = (const float*)d_in[5];
    const float* dw_b   = (const float*)d_in[6];
    const float* dwln_g = (const float*)d_in[7];
    const float* dwln_b = (const float*)d_in[8];
    const float* off_w  = (const float*)d_in[9];
    const float* off_b  = (const float*)d_in[10];
    const float* mask_w = (const float*)d_in[11];
    const float* mask_b = (const float*)d_in[12];
    const float* out_w  = (const float*)d_in[13];
    const float* out_b  = (const float*)d_in[14];
    const float* ln2_g  = (const float*)d_in[15];
    const float* ln2_b  = (const float*)d_in[16];
    const float* fc1_w  = (const float*)d_in[17];
    const float* fc1_b  = (const float*)d_in[18];
    const float* fc2_w  = (const float*)d_in[19];
    const float* fc2_b  = (const float*)d_in[20];
    float* out = (float*)d_out;

    float *xn, *xp, *x1, *omp, *yp, *x2, *hp, *h1, *wcat, *bcat;
    cudaGetSymbolAddress((void**)&xn,   g_xn);
    cudaGetSymbolAddress((void**)&xp,   g_xp);
    cudaGetSymbolAddress((void**)&x1,   g_x1);
    cudaGetSymbolAddress((void**)&omp,  g_om);
    cudaGetSymbolAddress((void**)&yp,   g_y);
    cudaGetSymbolAddress((void**)&x2,   g_x2);
    cudaGetSymbolAddress((void**)&hp,   g_h);
    cudaGetSymbolAddress((void**)&h1,   g_h1);
    cudaGetSymbolAddress((void**)&wcat, g_wcat);
    cudaGetSymbolAddress((void**)&bcat, g_bcat);

    static bool attr_done = false;
    if (!attr_done) {
        cudaFuncSetAttribute(gemm_tf32_db_kernel,
                             cudaFuncAttributeMaxDynamicSharedMemorySize,
                             GEMM_SMEM_BYTES);
        attr_done = true;
    }

    const int MROW = NTOK / 128;
    const dim3 gemm128(1, MROW);
    const dim3 gemm256(2, MROW);
    const dim3 gemm512(4, MROW);

    // 0. pack offset|mask weights (idempotent)
    prep_offmask_kernel<<<CC, NOM>>>(off_w, off_b, mask_w, mask_b, wcat, bcat);
    // 1. xn = LN1(x)
    ln_v4_kernel<<<NTOK / 8, 256>>>(x, ln1_g, ln1_b, xn);
    // 2. xp = xn @ in_w + in_b
    gemm_tf32_db_kernel<<<gemm128, 256, GEMM_SMEM_BYTES>>>(
        xn, in_w, in_b, nullptr, xp, nullptr, nullptr, nullptr, NTOK, CC, CC, 0);
    // 3. x1 = gelu(LN(dwconv(xn)))  (rolling-window v5)
    dwconv_ln_gelu_v5_kernel<<<1024, 256>>>(xn, dw_k, dw_b, dwln_g, dwln_b, x1);
    // 4. [offset | mask logits] = x1 @ wcat + bcat
    gemm_tf32_db_kernel<<<gemm256, 256, GEMM_SMEM_BYTES>>>(
        x1, wcat, bcat, nullptr, omp, nullptr, nullptr, nullptr, NTOK, NOM, CC, 0);
    // 5. y = deformable sample(xp, offsets, softmax(logits))
    dcn_sample_kernel<<<NTOK / 4, 128>>>(xp, omp, yp);
    // 6. x2 = y @ out_w + out_b + x ; h = LN2(x2)  (fused epilogue)
    gemm_tf32_db_kernel<<<gemm128, 256, GEMM_SMEM_BYTES>>>(
        yp, out_w, out_b, x, x2, hp, ln2_g, ln2_b, NTOK, CC, CC, 2);
    // 7. h1 = gelu(h @ fc1_w + fc1_b)
    gemm_tf32_db_kernel<<<gemm512, 256, GEMM_SMEM_BYTES>>>(
        hp, fc1_w, fc1_b, nullptr, h1, nullptr, nullptr, nullptr, NTOK, HID, CC, 1);
    // 8. out = h1 @ fc2_w + fc2_b + x2
    gemm_tf32_db_kernel<<<gemm128, 256, GEMM_SMEM_BYTES>>>(
        h1, fc2_w, fc2_b, x2, out, nullptr, nullptr, nullptr, NTOK, CC, HID, 0);
}

// round 15
// speedup vs baseline: 1.0104x; 1.0104x over previous
#include <cuda_runtime.h>
#include <math.h>
#include <stdint.h>

#define NB   4
#define HH   128
#define WW   128
#define CC   128
#define GG   8
#define GC   16
#define KK   9
#define NTOK (NB * HH * WW)   // 65536
#define HID  512
#define NOM  256              // padded offset(144)+mask(72) combined width
#define EPS  1e-5f

// ---------------- scratch (device globals; no allocation allowed) ------------
__device__ float g_xn [NTOK * CC];
__device__ float g_xp [NTOK * CC];
__device__ float g_x1 [NTOK * CC];
__device__ float g_om [NTOK * NOM];
__device__ float g_y  [NTOK * CC];
__device__ float g_x2 [NTOK * CC];
__device__ float g_h  [NTOK * CC];
__device__ float g_h1 [NTOK * HID];
__device__ float g_wcat[CC * NOM];       // [K=128][256] packed off_w|mask_w|0
__device__ float g_bcat[NOM];

__device__ __forceinline__ float gelu_exact(float x) {
    return 0.5f * x * (1.0f + erff(x * 0.70710678118654752f));
}

__device__ __forceinline__ void mma_tf32(float c[4], const uint32_t a[4], const uint32_t b[2]) {
    asm volatile(
        "mma.sync.aligned.m16n8k8.row.col.f32.tf32.tf32.f32 "
        "{%0,%1,%2,%3}, {%4,%5,%6,%7}, {%8,%9}, {%0,%1,%2,%3};"
        : "+f"(c[0]), "+f"(c[1]), "+f"(c[2]), "+f"(c[3])
        : "r"(a[0]), "r"(a[1]), "r"(a[2]), "r"(a[3]), "r"(b[0]), "r"(b[1]));
}

__device__ __forceinline__ void ldsm_x4(uint32_t& r0, uint32_t& r1, uint32_t& r2, uint32_t& r3,
                                        uint32_t addr) {
    asm volatile("ldmatrix.sync.aligned.m8n8.x4.shared.b16 {%0,%1,%2,%3}, [%4];"
                 : "=r"(r0), "=r"(r1), "=r"(r2), "=r"(r3) : "r"(addr));
}

__device__ __forceinline__ void cp_async16(uint32_t dst_smem, const void* src) {
    asm volatile("cp.async.cg.shared.global [%0], [%1], 16;" :: "r"(dst_smem), "l"(src));
}
__device__ __forceinline__ void cp_commit() { asm volatile("cp.async.commit_group;"); }
template <int N> __device__ __forceinline__ void cp_wait() {
    asm volatile("cp.async.wait_group %0;" :: "n"(N));
}

// ---------------- weight-packing prep: wcat = [off_w | mask_w | 0] ----------
__global__ __launch_bounds__(256) void prep_offmask_kernel(
    const float* __restrict__ off_w, const float* __restrict__ off_b,
    const float* __restrict__ mask_w, const float* __restrict__ mask_b,
    float* __restrict__ wcat, float* __restrict__ bcat)
{
    const int k = blockIdx.x;
    const int j = threadIdx.x;
    float v = 0.0f;
    if (j < 144)      v = off_w[k * 144 + j];
    else if (j < 216) v = mask_w[k * 72 + (j - 144)];
    wcat[k * NOM + j] = v;
    if (k == 0) {
        float bv = 0.0f;
        if (j < 144)      bv = off_b[j];
        else if (j < 216) bv = mask_b[j - 144];
        bcat[j] = bv;
    }
}

// -------- LayerNorm, warp per token, float4, shfl-only reduction ------------
__global__ __launch_bounds__(256) void ln_v4_kernel(
    const float* __restrict__ in, const float* __restrict__ g,
    const float* __restrict__ b, float* __restrict__ out)
{
    const int warp = threadIdx.x >> 5;
    const int lane = threadIdx.x & 31;
    const int tok  = blockIdx.x * 8 + warp;

    const float4 v = *(const float4*)&in[(size_t)tok * CC + lane * 4];
    float s  = v.x + v.y + v.z + v.w;
    float s2 = v.x * v.x + v.y * v.y + v.z * v.z + v.w * v.w;
    #pragma unroll
    for (int o = 16; o > 0; o >>= 1) {
        s  += __shfl_xor_sync(0xffffffffu, s,  o);
        s2 += __shfl_xor_sync(0xffffffffu, s2, o);
    }
    const float mean = s * (1.0f / CC);
    const float var  = s2 * (1.0f / CC) - mean * mean;
    const float rstd = rsqrtf(var + EPS);
    const float4 gg = *(const float4*)&g[lane * 4];
    const float4 bb = *(const float4*)&b[lane * 4];
    float4 o4;
    o4.x = (v.x - mean) * rstd * gg.x + bb.x;
    o4.y = (v.y - mean) * rstd * gg.y + bb.y;
    o4.z = (v.z - mean) * rstd * gg.z + bb.z;
    o4.w = (v.w - mean) * rstd * gg.w + bb.w;
    *(float4*)&out[(size_t)tok * CC + lane * 4] = o4;
}

// ------ dwconv3x3 + LN + GELU v6: rolling window, weights in shared ---------
// Warp = 8-token row segment, lane = channel quad. Same FMA order as v4/v5
// (ky outer, kx inner) -> bit-identical output. Weights in smem to cut ~36
// regs vs v5 (127 -> target <96) for 3 blocks/SM.
__global__ __launch_bounds__(256) void dwconv_ln_gelu_v6_kernel(
    const float* __restrict__ xn, const float* __restrict__ dwk,
    const float* __restrict__ dwb, const float* __restrict__ lg,
    const float* __restrict__ lb, float* __restrict__ out)
{
    __shared__ float s_wk[9 * CC];     // 4.6 KB
    for (int i = threadIdx.x; i < 9 * CC; i += 256) s_wk[i] = dwk[i];
    __syncthreads();

    const int warp = threadIdx.x >> 5;
    const int lane = threadIdx.x & 31;
    const int seg  = blockIdx.x * 8 + warp;          // 8192 segments
    const int row  = seg >> 4;                       // n*HH + h  (0..511)
    const int w0   = (seg & 15) * 8;
    const int h    = row & (HH - 1);
    const int c4   = lane * 4;

    const float* rowc = xn + ((size_t)row * WW) * CC + c4;
    const bool hup = (h >= 1), hdn = (h <= HH - 2);

    const float4 bia = *(const float4*)&dwb[c4];
    const float4 gg  = *(const float4*)&lg[c4];
    const float4 bb  = *(const float4*)&lb[c4];
    const float* wkp = s_wk + c4;

    const float4 z4 = make_float4(0.f, 0.f, 0.f, 0.f);
    float4 cL[3], cC[3], cR[3];

    auto load_col = [&](int wx, float4 v[3]) {
        if (wx < 0 || wx >= WW) { v[0] = z4; v[1] = z4; v[2] = z4; return; }
        const int off = wx * CC;
        v[0] = hup ? *(const float4*)(rowc + off - WW * CC) : z4;
        v[1] = *(const float4*)(rowc + off);
        v[2] = hdn ? *(const float4*)(rowc + off + WW * CC) : z4;
    };

    load_col(w0 - 1, cL);
    load_col(w0,     cC);

    #pragma unroll
    for (int t = 0; t < 8; t++) {
        load_col(w0 + t + 1, cR);

        float4 acc = bia;
        #pragma unroll
        for (int ky = 0; ky < 3; ky++) {
            const float4 k0 = *(const float4*)(wkp + (ky * 3 + 0) * CC);
            const float4 k1 = *(const float4*)(wkp + (ky * 3 + 1) * CC);
            const float4 k2 = *(const float4*)(wkp + (ky * 3 + 2) * CC);
            acc.x = fmaf(cL[ky].x, k0.x, acc.x);
            acc.y = fmaf(cL[ky].y, k0.y, acc.y);
            acc.z = fmaf(cL[ky].z, k0.z, acc.z);
            acc.w = fmaf(cL[ky].w, k0.w, acc.w);
            acc.x = fmaf(cC[ky].x, k1.x, acc.x);
            acc.y = fmaf(cC[ky].y, k1.y, acc.y);
            acc.z = fmaf(cC[ky].z, k1.z, acc.z);
            acc.w = fmaf(cC[ky].w, k1.w, acc.w);
            acc.x = fmaf(cR[ky].x, k2.x, acc.x);
            acc.y = fmaf(cR[ky].y, k2.y, acc.y);
            acc.z = fmaf(cR[ky].z, k2.z, acc.z);
            acc.w = fmaf(cR[ky].w, k2.w, acc.w);
        }

        float s  = acc.x + acc.y + acc.z + acc.w;
        float s2 = acc.x * acc.x + acc.y * acc.y + acc.z * acc.z + acc.w * acc.w;
        #pragma unroll
        for (int o = 16; o > 0; o >>= 1) {
            s  += __shfl_xor_sync(0xffffffffu, s,  o);
            s2 += __shfl_xor_sync(0xffffffffu, s2, o);
        }
        const float mean = s * (1.0f / CC);
        const float var  = s2 * (1.0f / CC) - mean * mean;
        const float rstd = rsqrtf(var + EPS);
        float4 o4;
        o4.x = gelu_exact((acc.x - mean) * rstd * gg.x + bb.x);
        o4.y = gelu_exact((acc.y - mean) * rstd * gg.y + bb.y);
        o4.z = gelu_exact((acc.z - mean) * rstd * gg.z + bb.z);
        o4.w = gelu_exact((acc.w - mean) * rstd * gg.w + bb.w);
        *(float4*)&out[((size_t)row * WW + w0 + t) * CC + c4] = o4;

        #pragma unroll
        for (int ky = 0; ky < 3; ky++) { cL[ky] = cC[ky]; cC[ky] = cR[ky]; }
    }
}

// ---- tf32 GEMM (ldmatrix A, LDS B) + optional fused-LN epilogue ------------
// BM=128, BN=128, BK=32; 256 thr = 8 warps (2 M x 4 N), warp tile 64x32.
// act: 0 = none, 1 = gelu, 2 = (res add, write C=x2) + LN -> D.
#define AS_STRIDE 36
#define BS_STRIDE 136
#define A_BUF (128 * AS_STRIDE)
#define B_BUF (32 * BS_STRIDE)
#define GEMM_SMEM_BYTES ((2 * A_BUF + 2 * B_BUF) * 4)   // 71680
#define SX_STRIDE 132

__global__ __launch_bounds__(256) void gemm_tf32_db_kernel(
    const float* __restrict__ A, const float* __restrict__ B,
    const float* __restrict__ bias, const float* __restrict__ res,
    float* __restrict__ C, float* __restrict__ D,
    const float* __restrict__ g2, const float* __restrict__ b2,
    int M, int N, int K, int act)
{
    extern __shared__ float smem[];
    float* sA = smem;
    float* sB = smem + 2 * A_BUF;

    const int tid  = threadIdx.x;
    const int warp = tid >> 5;
    const int lane = tid & 31;
    const int grp  = lane >> 2;
    const int t4   = lane & 3;
    const int wm   = warp >> 2;
    const int wn   = warp & 3;
    const int brow = blockIdx.y * 128;
    const int bcol = blockIdx.x * 128;

    const uint32_t sA_u = (uint32_t)__cvta_generic_to_shared(sA);
    const uint32_t sB_u = (uint32_t)__cvta_generic_to_shared(sB);
    const int KT = K >> 5;

    const int a_row = ((lane >> 3) & 1) * 8 + (lane & 7);
    const int a_col = (lane >> 4) * 4;

    auto load_tile = [&](int kt, int buf) {
        const int k0 = kt << 5;
        #pragma unroll
        for (int it = 0; it < 4; it++) {
            const int idx = it * 256 + tid;
            const int r = idx >> 3, c = idx & 7;
            cp_async16(sA_u + (buf * A_BUF + r * AS_STRIDE + c * 4) * 4,
                       &A[(size_t)(brow + r) * K + k0 + c * 4]);
        }
        #pragma unroll
        for (int it = 0; it < 4; it++) {
            const int idx = it * 256 + tid;
            const int kr = idx >> 5, c = idx & 31;
            cp_async16(sB_u + (buf * B_BUF + kr * BS_STRIDE + c * 4) * 4,
                       &B[(size_t)(k0 + kr) * N + bcol + c * 4]);
        }
        cp_commit();
    };

    float acc[4][4][4];
    #pragma unroll
    for (int i = 0; i < 4; i++)
        #pragma unroll
        for (int j = 0; j < 4; j++)
            #pragma unroll
            for (int q = 0; q < 4; q++) acc[i][j][q] = 0.0f;

    load_tile(0, 0);

    for (int kt = 0; kt < KT; kt++) {
        if (kt + 1 < KT) { load_tile(kt + 1, (kt + 1) & 1); cp_wait<1>(); }
        else             { cp_wait<0>(); }
        __syncthreads();

        const uint32_t Ab_u = sA_u + ((kt & 1) * A_BUF) * 4;
        const float*   Bb   = sB + (kt & 1) * B_BUF;

        #pragma unroll
        for (int kk = 0; kk < 4; kk++) {
            const int kb = kk * 8;
            uint32_t af[4][4], bf[4][2];
            #pragma unroll
            for (int i = 0; i < 4; i++) {
                const int m0 = wm * 64 + i * 16;
                ldsm_x4(af[i][0], af[i][1], af[i][2], af[i][3],
                        Ab_u + ((m0 + a_row) * AS_STRIDE + kb + a_col) * 4);
            }
            #pragma unroll
            for (int j = 0; j < 4; j++) {
                const int n0 = wn * 32 + j * 8 + grp;
                bf[j][0] = __float_as_uint(Bb[(kb + t4    ) * BS_STRIDE + n0]);
                bf[j][1] = __float_as_uint(Bb[(kb + t4 + 4) * BS_STRIDE + n0]);
            }
            #pragma unroll
            for (int i = 0; i < 4; i++)
                #pragma unroll
                for (int j = 0; j < 4; j++)
                    mma_tf32(acc[i][j], af[i], bf[j]);
        }
        __syncthreads();
    }

    if (act == 2) {
        float* sx = smem;   // dead tile buffers; [128][SX_STRIDE]
        #pragma unroll
        for (int i = 0; i < 4; i++) {
            const int rl0 = wm * 64 + i * 16 + grp;
            #pragma unroll
            for (int j = 0; j < 4; j++) {
                const int col = wn * 32 + j * 8 + 2 * t4;
                const float b0 = bias[col], b1 = bias[col + 1];
                #pragma unroll
                for (int half = 0; half < 2; half++) {
                    const int rl = rl0 + half * 8;
                    const int r  = brow + rl;
                    const float2 rr = *(const float2*)&res[(size_t)r * N + col];
                    const float v0 = acc[i][j][half * 2 + 0] + b0 + rr.x;
                    const float v1 = acc[i][j][half * 2 + 1] + b1 + rr.y;
                    *(float2*)&C[(size_t)r * N + col] = make_float2(v0, v1);
                    *(float2*)&sx[rl * SX_STRIDE + col] = make_float2(v0, v1);
                }
            }
        }
        __syncthreads();
        const float4 g4 = *(const float4*)&g2[lane * 4];
        const float4 b4 = *(const float4*)&b2[lane * 4];
        #pragma unroll
        for (int rr2 = 0; rr2 < 16; rr2++) {
            const int rl = warp * 16 + rr2;
            const float4 v = *(const float4*)&sx[rl * SX_STRIDE + lane * 4];
            float s  = v.x + v.y + v.z + v.w;
            float q  = v.x * v.x + v.y * v.y + v.z * v.z + v.w * v.w;
            #pragma unroll
            for (int o = 16; o > 0; o >>= 1) {
                s += __shfl_xor_sync(0xffffffffu, s, o);
                q += __shfl_xor_sync(0xffffffffu, q, o);
            }
            const float mean = s * (1.0f / CC);
            const float var  = q * (1.0f / CC) - mean * mean;
            const float rstd = rsqrtf(var + EPS);
            float4 o4;
            o4.x = (v.x - mean) * rstd * g4.x + b4.x;
            o4.y = (v.y - mean) * rstd * g4.y + b4.y;
            o4.z = (v.z - mean) * rstd * g4.z + b4.z;
            o4.w = (v.w - mean) * rstd * g4.w + b4.w;
            *(float4*)&D[(size_t)(brow + rl) * CC + lane * 4] = o4;
        }
        return;
    }

    #pragma unroll
    for (int i = 0; i < 4; i++) {
        const int r0 = brow + wm * 64 + i * 16 + grp;
        #pragma unroll
        for (int j = 0; j < 4; j++) {
            const int col = bcol + wn * 32 + j * 8 + 2 * t4;
            const float b0 = bias[col], b1 = bias[col + 1];
            #pragma unroll
            for (int half = 0; half < 2; half++) {
                const int r = r0 + half * 8;
                float v0 = acc[i][j][half * 2 + 0] + b0;
                float v1 = acc[i][j][half * 2 + 1] + b1;
                if (act == 1) { v0 = gelu_exact(v0); v1 = gelu_exact(v1); }
                if (res) {
                    const float2 rr = *(const float2*)&res[(size_t)r * N + col];
                    v0 += rr.x; v1 += rr.y;
                }
                *(float2*)&C[(size_t)r * N + col] = make_float2(v0, v1);
            }
        }
    }
}

// ------- deformable sampling + fused softmax; 1 warp per token, float4 ------
__global__ __launch_bounds__(256) void dcn_sample_kernel(
    const float* __restrict__ xp, const float* __restrict__ om,
    float* __restrict__ y)
{
    const int tt   = threadIdx.x >> 5;               // 0..7 token within block
    const int lane = threadIdx.x & 31;
    const int tok  = blockIdx.x * 8 + tt;
    const int n  = tok / (HH * WW);
    const int hw = tok % (HH * WW);
    const int h = hw / WW, w = hw % WW;

    __shared__ float s_om[8][216];
    const float* src = om + (size_t)tok * NOM;
    for (int i = lane; i < 216; i += 32) s_om[tt][i] = src[i];
    __syncwarp();

    if (lane < GG) {
        float* p = &s_om[tt][144 + lane * KK];
        float mx = -1e30f;
        #pragma unroll
        for (int k = 0; k < KK; k++) mx = fmaxf(mx, p[k]);
        float s = 0.0f, e[KK];
        #pragma unroll
        for (int k = 0; k < KK; k++) { e[k] = __expf(p[k] - mx); s += e[k]; }
        const float inv = 1.0f / s;
        #pragma unroll
        for (int k = 0; k < KK; k++) p[k] = e[k] * inv;
    }
    __syncwarp();

    const int g  = lane >> 2;
    const int c4 = lane & 3;
    const float* base = xp + ((size_t)n * HH * WW) * CC + g * GC + c4 * 4;
    float4 acc = make_float4(0.f, 0.f, 0.f, 0.f);

    #pragma unroll
    for (int k = 0; k < KK; k++) {
        const float ox = s_om[tt][(g * KK + k) * 2 + 0];
        const float oy = s_om[tt][(g * KK + k) * 2 + 1];
        const float mw = s_om[tt][144 + g * KK + k];
        const float px = (float)(w + 1 + (k / 3) - 1) + ox;
        const float py = (float)(h + 1 + (k % 3) - 1) + oy;
        const float x0f = floorf(px), y0f = floorf(py);
        const float tx = px - x0f, ty = py - y0f;
        const int x0 = (int)x0f, y0 = (int)y0f;

        const bool yi0 = (y0 >= 1) & (y0 <= HH);
        const bool yi1 = (y0 + 1 >= 1) & (y0 + 1 <= HH);
        const bool xi0 = (x0 >= 1) & (x0 <= WW);
        const bool xi1 = (x0 + 1 >= 1) & (x0 + 1 <= WW);

        float4 v00 = make_float4(0,0,0,0), v01 = v00, v10 = v00, v11 = v00;
        if (yi0 & xi0) v00 = *(const float4*)&base[((size_t)(y0 - 1) * WW + (x0 - 1)) * CC];
        if (yi0 & xi1) v01 = *(const float4*)&base[((size_t)(y0 - 1) * WW + (x0    )) * CC];
        if (yi1 & xi0) v10 = *(const float4*)&base[((size_t)(y0    ) * WW + (x0 - 1)) * CC];
        if (yi1 & xi1) v11 = *(const float4*)&base[((size_t)(y0    ) * WW + (x0    )) * CC];

        const float w00 = mw * (1.f - ty) * (1.f - tx);
        const float w01 = mw * (1.f - ty) * tx;
        const float w10 = mw * ty * (1.f - tx);
        const float w11 = mw * ty * tx;
        acc.x += w00 * v00.x + w01 * v01.x + w10 * v10.x + w11 * v11.x;
        acc.y += w00 * v00.y + w01 * v01.y + w10 * v10.y + w11 * v11.y;
        acc.z += w00 * v00.z + w01 * v01.z + w10 * v10.z + w11 * v11.z;
        acc.w += w00 * v00.w + w01 * v01.w + w10 * v10.w + w11 * v11.w;
    }
    *(float4*)&y[(size_t)tok * CC + g * GC + c4 * 4] = acc;
}

// ---------------------------------------------------------------------------
extern "C" void kernel_launch(void* const* d_in, const int* in_sizes, int n_in,
                              void* d_out, int out_size)
{
    const float* x      = (const float*)d_in[0];
    const float* ln1_g  = (const float*)d_in[1];
    const float* ln1_b  = (const float*)d_in[2];
    const float* in_w   = (const float*)d_in[3];
    const float* in_b   = (const float*)d_in[4];
    const float* dw_k   = (const float*)d_in[5];
    const float* dw_b   = (const float*)d_in[6];
    const float* dwln_g = (const float*)d_in[7];
    const float* dwln_b = (const float*)d_in[8];
    const float* off_w  = (const float*)d_in[9];
    const float* off_b  = (const float*)d_in[10];
    const float* mask_w = (const float*)d_in[11];
    const float* mask_b = (const float*)d_in[12];
    const float* out_w  = (const float*)d_in[13];
    const float* out_b  = (const float*)d_in[14];
    const float* ln2_g  = (const float*)d_in[15];
    const float* ln2_b  = (const float*)d_in[16];
    const float* fc1_w  = (const float*)d_in[17];
    const float* fc1_b  = (const float*)d_in[18];
    const float* fc2_w  = (const float*)d_in[19];
    const float* fc2_b  = (const float*)d_in[20];
    float* out = (float*)d_out;

    float *xn, *xp, *x1, *omp, *yp, *x2, *hp, *h1, *wcat, *bcat;
    cudaGetSymbolAddress((void**)&xn,   g_xn);
    cudaGetSymbolAddress((void**)&xp,   g_xp);
    cudaGetSymbolAddress((void**)&x1,   g_x1);
    cudaGetSymbolAddress((void**)&omp,  g_om);
    cudaGetSymbolAddress((void**)&yp,   g_y);
    cudaGetSymbolAddress((void**)&x2,   g_x2);
    cudaGetSymbolAddress((void**)&hp,   g_h);
    cudaGetSymbolAddress((void**)&h1,   g_h1);
    cudaGetSymbolAddress((void**)&wcat, g_wcat);
    cudaGetSymbolAddress((void**)&bcat, g_bcat);

    static bool attr_done = false;
    if (!attr_done) {
        cudaFuncSetAttribute(gemm_tf32_db_kernel,
                             cudaFuncAttributeMaxDynamicSharedMemorySize,
                             GEMM_SMEM_BYTES);
        attr_done = true;
    }

    const int MROW = NTOK / 128;
    const dim3 gemm128(1, MROW);
    const dim3 gemm256(2, MROW);
    const dim3 gemm512(4, MROW);

    // 0. pack offset|mask weights (idempotent)
    prep_offmask_kernel<<<CC, NOM>>>(off_w, off_b, mask_w, mask_b, wcat, bcat);
    // 1. xn = LN1(x)
    ln_v4_kernel<<<NTOK / 8, 256>>>(x, ln1_g, ln1_b, xn);
    // 2. xp = xn @ in_w + in_b
    gemm_tf32_db_kernel<<<gemm128, 256, GEMM_SMEM_BYTES>>>(
        xn, in_w, in_b, nullptr, xp, nullptr, nullptr, nullptr, NTOK, CC, CC, 0);
    // 3. x1 = gelu(LN(dwconv(xn)))  (rolling window, smem weights)
    dwconv_ln_gelu_v6_kernel<<<1024, 256>>>(xn, dw_k, dw_b, dwln_g, dwln_b, x1);
    // 4. [offset | mask logits] = x1 @ wcat + bcat
    gemm_tf32_db_kernel<<<gemm256, 256, GEMM_SMEM_BYTES>>>(
        x1, wcat, bcat, nullptr, omp, nullptr, nullptr, nullptr, NTOK, NOM, CC, 0);
    // 5. y = deformable sample(xp, offsets, softmax(logits))
    dcn_sample_kernel<<<NTOK / 8, 256>>>(xp, omp, yp);
    // 6. x2 = y @ out_w + out_b + x ; h = LN2(x2)  (fused epilogue)
    gemm_tf32_db_kernel<<<gemm128, 256, GEMM_SMEM_BYTES>>>(
        yp, out_w, out_b, x, x2, hp, ln2_g, ln2_b, NTOK, CC, CC, 2);
    // 7. h1 = gelu(h @ fc1_w + fc1_b)
    gemm_tf32_db_kernel<<<gemm512, 256, GEMM_SMEM_BYTES>>>(
        hp, fc1_w, fc1_b, nullptr, h1, nullptr, nullptr, nullptr, NTOK, HID, CC, 1);
    // 8. out = h1 @ fc2_w + fc2_b + x2
    gemm_tf32_db_kernel<<<gemm128, 256, GEMM_SMEM_BYTES>>>(
        h1, fc2_w, fc2_b, x2, out, nullptr, nullptr, nullptr, NTOK, CC, HID, 0);
}